// round 1
// baseline (speedup 1.0000x reference)
#include <cuda_runtime.h>
#include <cstdint>

// Problem constants
#define B_TOTAL  128
#define C_IN     32
#define C_OUT    8
#define S_TOTAL  8192

// Tiling
#define S_TILE   64      // s-values per block (16 float4 groups)
#define B_CHUNK  32      // batches per block
#define THREADS  128     // 8 o * 16 s4-groups

// Scratch for ws[j,s] = sum_i w1[i,j,s]  (1 MB)
__device__ float g_ws[C_IN * S_TOTAL];

// ---------------------------------------------------------------------------
// helpers
// ---------------------------------------------------------------------------
__device__ __forceinline__ float tanh_fast(float x) {
    float y;
    asm("tanh.approx.f32 %0, %1;" : "=f"(y) : "f"(x));
    return y;
}

// Accurate-enough tanh for the final output (rel err ~1e-6):
// tanh(x) = (e^{2x}-1)/(e^{2x}+1), clamped to avoid overflow.
__device__ __forceinline__ float tanh_acc(float x) {
    float xc = fminf(fmaxf(x, -20.0f), 20.0f);
    float e  = __expf(2.0f * xc);
    return __fdividef(e - 1.0f, e + 1.0f);
}

__device__ __forceinline__ float4 ld4(const float* p) {
    return *reinterpret_cast<const float4*>(p);
}
__device__ __forceinline__ void st4(float* p, float4 v) {
    *reinterpret_cast<float4*>(p) = v;
}

// ---------------------------------------------------------------------------
// Kernel 1: ws[j,s] = sum_i w1[i,j,s]
// w1 layout: [C_IN(i)][C_IN(j)][S]
// ---------------------------------------------------------------------------
__global__ __launch_bounds__(256) void ws_kernel(const float* __restrict__ w1) {
    int t = blockIdx.x * blockDim.x + threadIdx.x;   // 0 .. C_IN*S/4 - 1
    int j   = t >> 11;             // / 2048   (2048 float4 groups per j row)
    int grp = t & 2047;
    const float* p = w1 + (size_t)j * S_TOTAL + grp * 4;
    float4 acc = make_float4(0.f, 0.f, 0.f, 0.f);
#pragma unroll
    for (int i = 0; i < C_IN; i++) {
        float4 v = ld4(p + (size_t)i * C_IN * S_TOTAL);
        acc.x += v.x; acc.y += v.y; acc.z += v.z; acc.w += v.w;
    }
    st4(&g_ws[(size_t)j * S_TOTAL + grp * 4], acc);
}

// ---------------------------------------------------------------------------
// Kernel 2: fused stage1 + stage2.
// Block: s-tile of 64, batch chunk of 32. w2 tile lives in registers
// (per-thread: w2[o, 0..31, s4] = 32 float4). h staged in smem, reused by
// all 8 output channels via broadcast LDS.
// ---------------------------------------------------------------------------
__global__ __launch_bounds__(THREADS) void fused_kernel(
    const float* __restrict__ x,     // [B][C_IN][S]
    const float* __restrict__ w2,    // [C_OUT][C_IN][S]
    const float* __restrict__ bias,  // [C_OUT][S]
    float* __restrict__ out)         // [B][C_OUT][S]
{
    __shared__ float h_s[C_IN][S_TILE];   // 8 KB

    const int t     = threadIdx.x;
    const int sBase = blockIdx.x * S_TILE;
    const int bBase = blockIdx.y * B_CHUNK;

    // ---- phase-A mapping (x load / h produce): thread -> (jA, 4 s4-groups)
    const int jA  = t >> 2;        // 0..31
    const int sgA = t & 3;         // group base; groups sgA, sgA+4, sgA+8, sgA+12

    // ---- phase-B mapping (contraction): thread -> (oB, one s4-group)
    const int oB  = t >> 4;        // 0..7
    const int sgB = t & 15;        // 0..15

    // ws for this thread's phase-A lanes (loaded once)
    float4 wsr[4];
#pragma unroll
    for (int u = 0; u < 4; u++) {
        int g = sgA + 4 * u;
        wsr[u] = ld4(&g_ws[(size_t)jA * S_TOTAL + sBase + g * 4]);
    }

    // w2 slice for this thread's (oB, s4) — 32 float4 in registers
    float4 w2r[32];
    {
        const float* p = w2 + (size_t)oB * C_IN * S_TOTAL + sBase + sgB * 4;
#pragma unroll
        for (int j = 0; j < C_IN; j++)
            w2r[j] = ld4(p + (size_t)j * S_TOTAL);
    }

    // bias (same for every batch)
    const float4 biasr = ld4(&bias[(size_t)oB * S_TOTAL + sBase + sgB * 4]);

    // prefetch x for b = 0
    float4 xr[4];
    {
        const float* p = x + ((size_t)bBase * C_IN + jA) * S_TOTAL + sBase;
#pragma unroll
        for (int u = 0; u < 4; u++)
            xr[u] = ld4(p + (sgA + 4 * u) * 4);
    }

    for (int b = 0; b < B_CHUNK; b++) {
        // ---- phase A: h = tanh(x * ws) -> smem
#pragma unroll
        for (int u = 0; u < 4; u++) {
            int g = sgA + 4 * u;
            float4 hv;
            hv.x = tanh_fast(xr[u].x * wsr[u].x);
            hv.y = tanh_fast(xr[u].y * wsr[u].y);
            hv.z = tanh_fast(xr[u].z * wsr[u].z);
            hv.w = tanh_fast(xr[u].w * wsr[u].w);
            st4(&h_s[jA][g * 4], hv);
        }
        __syncthreads();

        // prefetch x for next batch (hides DRAM latency under phase B)
        if (b + 1 < B_CHUNK) {
            const float* p = x + ((size_t)(bBase + b + 1) * C_IN + jA) * S_TOTAL + sBase;
#pragma unroll
            for (int u = 0; u < 4; u++)
                xr[u] = ld4(p + (sgA + 4 * u) * 4);
        }

        // ---- phase B: acc[o,s4] = bias + sum_j h[j,s4] * w2[o,j,s4]
        float4 acc = biasr;
#pragma unroll
        for (int j = 0; j < C_IN; j++) {
            float4 hv = ld4(&h_s[j][sgB * 4]);
            acc.x += hv.x * w2r[j].x;
            acc.y += hv.y * w2r[j].y;
            acc.z += hv.z * w2r[j].z;
            acc.w += hv.w * w2r[j].w;
        }

        float4 ov;
        ov.x = tanh_acc(acc.x);
        ov.y = tanh_acc(acc.y);
        ov.z = tanh_acc(acc.z);
        ov.w = tanh_acc(acc.w);
        st4(&out[(((size_t)(bBase + b) * C_OUT + oB) * S_TOTAL) + sBase + sgB * 4], ov);

        __syncthreads();   // protect h_s before next batch overwrites it
    }
}

// ---------------------------------------------------------------------------
// launch
// ---------------------------------------------------------------------------
extern "C" void kernel_launch(void* const* d_in, const int* in_sizes, int n_in,
                              void* d_out, int out_size) {
    const float* x    = (const float*)d_in[0];
    const float* w1   = (const float*)d_in[1];
    const float* w2   = (const float*)d_in[2];
    const float* bias = (const float*)d_in[3];
    float* out = (float*)d_out;

    // Kernel 1: ws = sum_i w1   (65536 float4 tasks)
    ws_kernel<<<(C_IN * S_TOTAL / 4) / 256, 256>>>(w1);

    // Kernel 2: fused stages
    dim3 grid(S_TOTAL / S_TILE, B_TOTAL / B_CHUNK);   // (128, 4)
    fused_kernel<<<grid, THREADS>>>(x, w2, bias, out);
}